// round 1
// baseline (speedup 1.0000x reference)
#include <cuda_runtime.h>
#include <math.h>

#define NNODES 100000
#define NEDGES 3200000
#define NFEAT  512
#define NH     256
#define NC     40
#define NL     8
#define ALPHA  0.1f

// ---------------- scratch (device globals; no allocation allowed) ----------------
__device__ float g_h  [(size_t)NNODES * NH];   // current hidden state
__device__ float g_h0 [(size_t)NNODES * NH];   // initial hidden state (residual)
__device__ float g_tmp[(size_t)NNODES * NH];   // support buffer
__device__ int   g_rowptr[NNODES + 1];
__device__ int   g_cursor[NNODES];
__device__ int   g_colidx[NEDGES];
__device__ float g_evals [NEDGES];
__device__ int   g_partial[1024];

// ---------------- CSR construction ----------------
__global__ void k_zero_counts(int n) {
    for (int i = blockIdx.x * blockDim.x + threadIdx.x; i < n; i += gridDim.x * blockDim.x)
        g_rowptr[i] = 0;
}

__global__ void k_hist(const int* __restrict__ rows, int e) {
    for (int i = blockIdx.x * blockDim.x + threadIdx.x; i < e; i += gridDim.x * blockDim.x)
        atomicAdd(&g_rowptr[rows[i] + 1], 1);
}

// inclusive scan over g_rowptr[0..n), blocks of 1024
__global__ void k_scan_block(int n) {
    __shared__ int s[1024];
    int i = blockIdx.x * 1024 + threadIdx.x;
    int v = (i < n) ? g_rowptr[i] : 0;
    s[threadIdx.x] = v;
    __syncthreads();
    #pragma unroll
    for (int off = 1; off < 1024; off <<= 1) {
        int t = (threadIdx.x >= off) ? s[threadIdx.x - off] : 0;
        __syncthreads();
        s[threadIdx.x] += t;
        __syncthreads();
    }
    if (i < n) g_rowptr[i] = s[threadIdx.x];
    if (threadIdx.x == 1023) g_partial[blockIdx.x] = s[1023];
}

__global__ void k_scan_partials(int nb) {
    __shared__ int s[1024];
    int v = (threadIdx.x < nb) ? g_partial[threadIdx.x] : 0;
    s[threadIdx.x] = v;
    __syncthreads();
    #pragma unroll
    for (int off = 1; off < 1024; off <<= 1) {
        int t = (threadIdx.x >= off) ? s[threadIdx.x - off] : 0;
        __syncthreads();
        s[threadIdx.x] += t;
        __syncthreads();
    }
    if (threadIdx.x < nb) g_partial[threadIdx.x] = s[threadIdx.x];
}

__global__ void k_scan_add(int n) {
    int i = blockIdx.x * 1024 + threadIdx.x;
    if (i < n && blockIdx.x > 0) g_rowptr[i] += g_partial[blockIdx.x - 1];
}

__global__ void k_cursor(int n) {
    for (int i = blockIdx.x * blockDim.x + threadIdx.x; i < n; i += gridDim.x * blockDim.x)
        g_cursor[i] = g_rowptr[i];
}

__global__ void k_scatter(const int* __restrict__ rows, const int* __restrict__ cols,
                          const float* __restrict__ vals, int e) {
    for (int i = blockIdx.x * blockDim.x + threadIdx.x; i < e; i += gridDim.x * blockDim.x) {
        int r = rows[i];
        int p = atomicAdd(&g_cursor[r], 1);
        g_colidx[p] = cols[i];
        g_evals[p]  = vals[i];
    }
}

// ---------------- SpMM + residual combine ----------------
// support[row,:] = (1-alpha) * sum_e val_e * h[col_e,:] + alpha * h0[row,:]
__global__ void k_spmm_combine(const float* __restrict__ h, const float* __restrict__ h0,
                               float* __restrict__ out) {
    int row = blockIdx.x;
    int f   = threadIdx.x;           // 0..255 : feature index
    int beg = g_rowptr[row];
    int end = g_rowptr[row + 1];
    __shared__ int   scol[128];
    __shared__ float sval[128];
    float acc = 0.f;
    for (int base = beg; base < end; base += 128) {
        int cnt = min(128, end - base);
        if (f < cnt) { scol[f] = g_colidx[base + f]; sval[f] = g_evals[base + f]; }
        __syncthreads();
        for (int i = 0; i < cnt; ++i)
            acc += sval[i] * h[(size_t)scol[i] * NH + f];
        __syncthreads();
    }
    out[(size_t)row * NH + f] = (1.f - ALPHA) * acc + ALPHA * h0[(size_t)row * NH + f];
}

// ---------------- tiled fp32 GEMM with fused epilogues ----------------
// mode 0: C = relu(A@B + bias[n]); if C2 != nullptr, also write to C2
// mode 1: C = relu(th*(A@B) + (1-th)*R[m,n])
// mode 2: C = A@B + bias[n]
#define BM 64
#define BN 64
#define BK 16

__global__ void k_gemm(const float* __restrict__ A, const float* __restrict__ B,
                       const float* __restrict__ bias, const float* __restrict__ R,
                       float th, float* __restrict__ C, float* __restrict__ C2,
                       int M, int K, int Nn, int mode) {
    __shared__ float As[BK][BM];
    __shared__ float Bs[BK][BN];
    int tid = threadIdx.x;           // 256 threads
    int tx = tid & 15, ty = tid >> 4;
    int m0 = blockIdx.x * BM;
    int n0 = blockIdx.y * BN;

    int arow  = tid >> 2;            // 0..63
    int acol4 = (tid & 3) * 4;       // 0,4,8,12
    int brow  = tid >> 4;            // 0..15
    int bcol4 = (tid & 15) * 4;      // 0..60

    float acc[4][4];
    #pragma unroll
    for (int i = 0; i < 4; ++i)
        #pragma unroll
        for (int j = 0; j < 4; ++j) acc[i][j] = 0.f;

    for (int k0 = 0; k0 < K; k0 += BK) {
        float4 av = make_float4(0.f, 0.f, 0.f, 0.f);
        int gm = m0 + arow;
        if (gm < M)
            av = *reinterpret_cast<const float4*>(&A[(size_t)gm * K + k0 + acol4]);
        As[acol4 + 0][arow] = av.x;
        As[acol4 + 1][arow] = av.y;
        As[acol4 + 2][arow] = av.z;
        As[acol4 + 3][arow] = av.w;

        float4 bv = make_float4(0.f, 0.f, 0.f, 0.f);
        int gn = n0 + bcol4;
        if (gn < Nn)
            bv = *reinterpret_cast<const float4*>(&B[(size_t)(k0 + brow) * Nn + gn]);
        *reinterpret_cast<float4*>(&Bs[brow][bcol4]) = bv;
        __syncthreads();

        #pragma unroll
        for (int k = 0; k < BK; ++k) {
            float4 ra = *reinterpret_cast<const float4*>(&As[k][ty * 4]);
            float4 rb = *reinterpret_cast<const float4*>(&Bs[k][tx * 4]);
            float fa[4] = {ra.x, ra.y, ra.z, ra.w};
            float fb[4] = {rb.x, rb.y, rb.z, rb.w};
            #pragma unroll
            for (int i = 0; i < 4; ++i)
                #pragma unroll
                for (int j = 0; j < 4; ++j)
                    acc[i][j] += fa[i] * fb[j];
        }
        __syncthreads();
    }

    #pragma unroll
    for (int i = 0; i < 4; ++i) {
        int m = m0 + ty * 4 + i;
        if (m >= M) continue;
        #pragma unroll
        for (int j = 0; j < 4; ++j) {
            int n = n0 + tx * 4 + j;
            if (n >= Nn) continue;
            float v = acc[i][j];
            if (mode == 0) {
                v = fmaxf(v + bias[n], 0.f);
            } else if (mode == 1) {
                v = th * v + (1.f - th) * R[(size_t)m * Nn + n];
                v = fmaxf(v, 0.f);
            } else {
                v = v + bias[n];
            }
            C[(size_t)m * Nn + n] = v;
            if (C2) C2[(size_t)m * Nn + n] = v;
        }
    }
}

// ---------------- launch ----------------
extern "C" void kernel_launch(void* const* d_in, const int* in_sizes, int n_in,
                              void* d_out, int out_size) {
    const float* features = (const float*)d_in[0];
    const int*   erows    = (const int*)  d_in[1];
    const int*   ecols    = (const int*)  d_in[2];
    const float* evals    = (const float*)d_in[3];
    const float* W_in     = (const float*)d_in[4];
    const float* b_in     = (const float*)d_in[5];
    const float* convW    = (const float*)d_in[6];
    const float* W_out    = (const float*)d_in[7];
    const float* b_out    = (const float*)d_in[8];
    float* out = (float*)d_out;

    const int E = in_sizes[1];
    const int Mn = NNODES;

    float* d_h;   cudaGetSymbolAddress((void**)&d_h,   g_h);
    float* d_h0;  cudaGetSymbolAddress((void**)&d_h0,  g_h0);
    float* d_tmp; cudaGetSymbolAddress((void**)&d_tmp, g_tmp);

    // ---- build CSR ----
    int np1 = Mn + 1;
    k_zero_counts<<<(np1 + 255) / 256, 256>>>(np1);
    k_hist<<<(E + 255) / 256, 256>>>(erows, E);
    int nscan_blocks = (np1 + 1023) / 1024;
    k_scan_block<<<nscan_blocks, 1024>>>(np1);
    k_scan_partials<<<1, 1024>>>(nscan_blocks);
    k_scan_add<<<nscan_blocks, 1024>>>(np1);
    k_cursor<<<(Mn + 255) / 256, 256>>>(Mn);
    k_scatter<<<(E + 255) / 256, 256>>>(erows, ecols, evals, E);

    // ---- input layer: h = relu(F @ W_in + b_in); h0 = h ----
    {
        dim3 grid((Mn + BM - 1) / BM, (NH + BN - 1) / BN);
        k_gemm<<<grid, 256>>>(features, W_in, b_in, nullptr, 0.f,
                              d_h, d_h0, Mn, NFEAT, NH, 0);
    }

    // ---- GCNII layers ----
    for (int l = 0; l < NL; ++l) {
        float theta = logf(0.5f / (float)(l + 1) + 1.0f);
        // support = 0.9 * (G @ h) + 0.1 * h0   -> g_tmp
        k_spmm_combine<<<Mn, NH>>>(d_h, d_h0, d_tmp);
        // h = relu(theta * (support @ W_l) + (1 - theta) * support)
        dim3 grid((Mn + BM - 1) / BM, (NH + BN - 1) / BN);
        k_gemm<<<grid, 256>>>(d_tmp, convW + (size_t)l * NH * NH, nullptr, d_tmp,
                              theta, d_h, nullptr, Mn, NH, NH, 1);
    }

    // ---- output layer: out = h @ W_out + b_out ----
    {
        dim3 grid((Mn + BM - 1) / BM, (NC + BN - 1) / BN);
        k_gemm<<<grid, 256>>>(d_h, W_out, b_out, nullptr, 0.f,
                              out, nullptr, Mn, NH, NC, 2);
    }
}

// round 3
// speedup vs baseline: 2.0822x; 2.0822x over previous
#include <cuda_runtime.h>
#include <math.h>
#include <stdint.h>

#define NNODES 100000
#define NEDGES 3200000
#define NFEAT  512
#define NH     256
#define NC     40
#define NL     8
#define ALPHA  0.1f

// ---------------- scratch (device globals; no allocation allowed) ----------------
__device__ __align__(16) float g_h  [(size_t)NNODES * NH];
__device__ __align__(16) float g_h0 [(size_t)NNODES * NH];
__device__ __align__(16) float g_tmp[(size_t)NNODES * NH];
__device__ int   g_rowptr[NNODES + 1];
__device__ int   g_cursor[NNODES];
__device__ int   g_colidx[NEDGES];
__device__ float g_evals [NEDGES];
__device__ int   g_partial[1024];

__device__ __forceinline__ float tf32_rna(float x) {
    uint32_t u;
    asm("cvt.rna.tf32.f32 %0, %1;" : "=r"(u) : "f"(x));
    return __uint_as_float(u);
}

// ---------------- CSR construction ----------------
__global__ void k_zero_counts(int n) {
    for (int i = blockIdx.x * blockDim.x + threadIdx.x; i < n; i += gridDim.x * blockDim.x)
        g_rowptr[i] = 0;
}
__global__ void k_hist(const int* __restrict__ rows, int e) {
    for (int i = blockIdx.x * blockDim.x + threadIdx.x; i < e; i += gridDim.x * blockDim.x)
        atomicAdd(&g_rowptr[rows[i] + 1], 1);
}
__global__ void k_scan_block(int n) {
    __shared__ int s[1024];
    int i = blockIdx.x * 1024 + threadIdx.x;
    int v = (i < n) ? g_rowptr[i] : 0;
    s[threadIdx.x] = v;
    __syncthreads();
    #pragma unroll
    for (int off = 1; off < 1024; off <<= 1) {
        int t = (threadIdx.x >= off) ? s[threadIdx.x - off] : 0;
        __syncthreads();
        s[threadIdx.x] += t;
        __syncthreads();
    }
    if (i < n) g_rowptr[i] = s[threadIdx.x];
    if (threadIdx.x == 1023) g_partial[blockIdx.x] = s[1023];
}
__global__ void k_scan_partials(int nb) {
    __shared__ int s[1024];
    int v = (threadIdx.x < nb) ? g_partial[threadIdx.x] : 0;
    s[threadIdx.x] = v;
    __syncthreads();
    #pragma unroll
    for (int off = 1; off < 1024; off <<= 1) {
        int t = (threadIdx.x >= off) ? s[threadIdx.x - off] : 0;
        __syncthreads();
        s[threadIdx.x] += t;
        __syncthreads();
    }
    if (threadIdx.x < nb) g_partial[threadIdx.x] = s[threadIdx.x];
}
__global__ void k_scan_add(int n) {
    int i = blockIdx.x * 1024 + threadIdx.x;
    if (i < n && blockIdx.x > 0) g_rowptr[i] += g_partial[blockIdx.x - 1];
}
__global__ void k_cursor(int n) {
    for (int i = blockIdx.x * blockDim.x + threadIdx.x; i < n; i += gridDim.x * blockDim.x)
        g_cursor[i] = g_rowptr[i];
}
__global__ void k_scatter(const int* __restrict__ rows, const int* __restrict__ cols,
                          const float* __restrict__ vals, int e) {
    for (int i = blockIdx.x * blockDim.x + threadIdx.x; i < e; i += gridDim.x * blockDim.x) {
        int r = rows[i];
        int p = atomicAdd(&g_cursor[r], 1);
        g_colidx[p] = cols[i];
        g_evals[p]  = vals[i];
    }
}

// ---------------- SpMM + residual: out = 0.9*(G@h) + 0.1*h0 ----------------
// 128 threads/block, 2 rows/block, 64 threads (one float4 each) per row.
__global__ void k_spmm_combine(const float* __restrict__ h, const float* __restrict__ h0,
                               float* __restrict__ out) {
    int row = blockIdx.x * 2 + (threadIdx.x >> 6);
    int f   = threadIdx.x & 63;
    const float4* __restrict__ h4  = (const float4*)h;
    const float4* __restrict__ h04 = (const float4*)h0;
    float4* __restrict__ o4 = (float4*)out;

    int beg = g_rowptr[row], end = g_rowptr[row + 1];
    float4 acc = make_float4(0.f, 0.f, 0.f, 0.f);
    int e = beg;
    for (; e + 4 <= end; e += 4) {
        int   c0 = g_colidx[e],     c1 = g_colidx[e + 1];
        int   c2 = g_colidx[e + 2], c3 = g_colidx[e + 3];
        float v0 = g_evals[e],      v1 = g_evals[e + 1];
        float v2 = g_evals[e + 2],  v3 = g_evals[e + 3];
        float4 x0 = h4[(size_t)c0 * 64 + f];
        float4 x1 = h4[(size_t)c1 * 64 + f];
        float4 x2 = h4[(size_t)c2 * 64 + f];
        float4 x3 = h4[(size_t)c3 * 64 + f];
        acc.x += v0 * x0.x + v1 * x1.x + v2 * x2.x + v3 * x3.x;
        acc.y += v0 * x0.y + v1 * x1.y + v2 * x2.y + v3 * x3.y;
        acc.z += v0 * x0.z + v1 * x1.z + v2 * x2.z + v3 * x3.z;
        acc.w += v0 * x0.w + v1 * x1.w + v2 * x2.w + v3 * x3.w;
    }
    for (; e < end; ++e) {
        int c = g_colidx[e];
        float v = g_evals[e];
        float4 x = h4[(size_t)c * 64 + f];
        acc.x += v * x.x; acc.y += v * x.y; acc.z += v * x.z; acc.w += v * x.w;
    }
    float4 z = h04[(size_t)row * 64 + f];
    float4 o;
    o.x = (1.f - ALPHA) * acc.x + ALPHA * z.x;
    o.y = (1.f - ALPHA) * acc.y + ALPHA * z.y;
    o.z = (1.f - ALPHA) * acc.z + ALPHA * z.z;
    o.w = (1.f - ALPHA) * acc.w + ALPHA * z.w;
    o4[(size_t)row * 64 + f] = o;
}

// ---------------- tf32 mma.sync GEMM ----------------
// C[M,Nn] = A[M,K] @ B[K,Nn]  (both row-major; B fed as mma's col-major operand)
// mode 0: C = relu(D + bias), C2 = C
// mode 1: C = relu(th*D + (1-th)*R)
// mode 2: C = D + bias
#define BM 128
#define BN 128
#define KC 32
#define ASTRIDE 36
#define BSTRIDE 136
#define A_ELEMS (BM * ASTRIDE)               // per buffer, floats
#define B_ELEMS (KC * BSTRIDE)
#define SMEM_BYTES ((2 * A_ELEMS + 2 * B_ELEMS) * 4)

__device__ __forceinline__ void mma_tf32(float& c0, float& c1, float& c2, float& c3,
                                         uint32_t a0, uint32_t a1, uint32_t a2, uint32_t a3,
                                         uint32_t b0, uint32_t b1) {
    asm volatile(
        "mma.sync.aligned.m16n8k8.row.col.f32.tf32.tf32.f32 "
        "{%0,%1,%2,%3}, {%4,%5,%6,%7}, {%8,%9}, {%0,%1,%2,%3};"
        : "+f"(c0), "+f"(c1), "+f"(c2), "+f"(c3)
        : "r"(a0), "r"(a1), "r"(a2), "r"(a3), "r"(b0), "r"(b1));
}

__device__ __forceinline__ float4 cvt4(float4 v) {
    v.x = tf32_rna(v.x); v.y = tf32_rna(v.y);
    v.z = tf32_rna(v.z); v.w = tf32_rna(v.w);
    return v;
}

__global__ void __launch_bounds__(256, 1)
k_tgemm(const float* __restrict__ A, const float* __restrict__ B,
        const float* __restrict__ bias, const float* __restrict__ R,
        float th, float* __restrict__ C, float* __restrict__ C2,
        int M, int K, int Nn, int mode) {
    extern __shared__ float sm[];
    float* smA = sm;                       // [2][BM][ASTRIDE]
    float* smB = sm + 2 * A_ELEMS;         // [2][KC][BSTRIDE]

    int tid  = threadIdx.x;
    int wid  = tid >> 5, lane = tid & 31;
    int g    = lane >> 2, t = lane & 3;
    int wm   = wid & 1;                    // 2 warps in m: 64 rows each
    int wn   = wid >> 1;                   // 4 warps in n: 32 cols each
    int m0   = blockIdx.x * BM;
    int n0   = blockIdx.y * BN;
    int nc   = K / KC;

    float c[4][4][4];
    #pragma unroll
    for (int i = 0; i < 4; ++i)
        #pragma unroll
        for (int j = 0; j < 4; ++j)
            #pragma unroll
            for (int q = 0; q < 4; ++q) c[i][j][q] = 0.f;

    // ---- stage chunk 0 directly to smem buffer 0 ----
    {
        #pragma unroll
        for (int p = 0; p < 4; ++p) {
            int idx = tid + p * 256;
            int r = idx >> 3, c4 = (idx & 7) << 2;
            float4 v = make_float4(0.f, 0.f, 0.f, 0.f);
            int gm = m0 + r;
            if (gm < M) v = *reinterpret_cast<const float4*>(A + (size_t)gm * K + c4);
            *reinterpret_cast<float4*>(&smA[r * ASTRIDE + c4]) = cvt4(v);
        }
        #pragma unroll
        for (int p = 0; p < 4; ++p) {
            int idx = tid + p * 256;
            int r = idx >> 5, c4 = (idx & 31) << 2;
            int gn = n0 + c4;
            float4 v = make_float4(0.f, 0.f, 0.f, 0.f);
            if (gn + 3 < Nn) {
                v = *reinterpret_cast<const float4*>(B + (size_t)r * Nn + gn);
            } else if (gn < Nn) {
                float tmp[4] = {0.f, 0.f, 0.f, 0.f};
                for (int q = 0; q < 4; ++q)
                    if (gn + q < Nn) tmp[q] = B[(size_t)r * Nn + gn + q];
                v = make_float4(tmp[0], tmp[1], tmp[2], tmp[3]);
            }
            *reinterpret_cast<float4*>(&smB[r * BSTRIDE + c4]) = cvt4(v);
        }
    }
    __syncthreads();

    for (int ch = 0; ch < nc; ++ch) {
        int buf = ch & 1;
        const float* As = smA + buf * A_ELEMS;
        const float* Bs = smB + buf * B_ELEMS;

        // prefetch next chunk into registers
        float4 pa[4], pb[4];
        bool more = (ch + 1 < nc);
        if (more) {
            int k0 = (ch + 1) * KC;
            #pragma unroll
            for (int p = 0; p < 4; ++p) {
                int idx = tid + p * 256;
                int r = idx >> 3, c4 = (idx & 7) << 2;
                pa[p] = make_float4(0.f, 0.f, 0.f, 0.f);
                int gm = m0 + r;
                if (gm < M)
                    pa[p] = *reinterpret_cast<const float4*>(A + (size_t)gm * K + k0 + c4);
            }
            #pragma unroll
            for (int p = 0; p < 4; ++p) {
                int idx = tid + p * 256;
                int r = idx >> 5, c4 = (idx & 31) << 2;
                int gn = n0 + c4;
                pb[p] = make_float4(0.f, 0.f, 0.f, 0.f);
                if (gn + 3 < Nn) {
                    pb[p] = *reinterpret_cast<const float4*>(B + (size_t)(k0 + r) * Nn + gn);
                } else if (gn < Nn) {
                    float tmp[4] = {0.f, 0.f, 0.f, 0.f};
                    for (int q = 0; q < 4; ++q)
                        if (gn + q < Nn) tmp[q] = B[(size_t)(k0 + r) * Nn + gn + q];
                    pb[p] = make_float4(tmp[0], tmp[1], tmp[2], tmp[3]);
                }
            }
        }

        // mma over current buffer
        #pragma unroll
        for (int ks = 0; ks < 4; ++ks) {
            int kk = ks * 8;
            uint32_t af[4][4];
            #pragma unroll
            for (int mf = 0; mf < 4; ++mf) {
                int r = wm * 64 + mf * 16 + g;
                af[mf][0] = __float_as_uint(As[(r    ) * ASTRIDE + kk + t    ]);
                af[mf][1] = __float_as_uint(As[(r + 8) * ASTRIDE + kk + t    ]);
                af[mf][2] = __float_as_uint(As[(r    ) * ASTRIDE + kk + t + 4]);
                af[mf][3] = __float_as_uint(As[(r + 8) * ASTRIDE + kk + t + 4]);
            }
            uint32_t bf[4][2];
            #pragma unroll
            for (int nf = 0; nf < 4; ++nf) {
                int ncol = wn * 32 + nf * 8 + g;
                bf[nf][0] = __float_as_uint(Bs[(kk + t    ) * BSTRIDE + ncol]);
                bf[nf][1] = __float_as_uint(Bs[(kk + t + 4) * BSTRIDE + ncol]);
            }
            #pragma unroll
            for (int mf = 0; mf < 4; ++mf)
                #pragma unroll
                for (int nf = 0; nf < 4; ++nf)
                    mma_tf32(c[mf][nf][0], c[mf][nf][1], c[mf][nf][2], c[mf][nf][3],
                             af[mf][0], af[mf][1], af[mf][2], af[mf][3],
                             bf[nf][0], bf[nf][1]);
        }

        // write prefetched regs to the other buffer
        if (more) {
            float* Ad = smA + (buf ^ 1) * A_ELEMS;
            float* Bd = smB + (buf ^ 1) * B_ELEMS;
            #pragma unroll
            for (int p = 0; p < 4; ++p) {
                int idx = tid + p * 256;
                int r = idx >> 3, c4 = (idx & 7) << 2;
                *reinterpret_cast<float4*>(&Ad[r * ASTRIDE + c4]) = cvt4(pa[p]);
            }
            #pragma unroll
            for (int p = 0; p < 4; ++p) {
                int idx = tid + p * 256;
                int r = idx >> 5, c4 = (idx & 31) << 2;
                *reinterpret_cast<float4*>(&Bd[r * BSTRIDE + c4]) = cvt4(pb[p]);
            }
        }
        __syncthreads();
    }

    // ---- epilogue ----
    float oth = 1.f - th;
    #pragma unroll
    for (int mf = 0; mf < 4; ++mf) {
        int r0 = m0 + wm * 64 + mf * 16 + g;
        #pragma unroll
        for (int nf = 0; nf < 4; ++nf) {
            int ncol = n0 + wn * 32 + nf * 8 + 2 * t;
            #pragma unroll
            for (int half = 0; half < 2; ++half) {
                int m = r0 + half * 8;
                if (m >= M) continue;
                float d0 = c[mf][nf][half * 2 + 0];
                float d1 = c[mf][nf][half * 2 + 1];
                if (mode == 0) {
                    float o0 = fmaxf(d0 + bias[ncol], 0.f);
                    float o1 = fmaxf(d1 + bias[ncol + 1], 0.f);
                    float2 o = make_float2(o0, o1);
                    *reinterpret_cast<float2*>(C  + (size_t)m * Nn + ncol) = o;
                    *reinterpret_cast<float2*>(C2 + (size_t)m * Nn + ncol) = o;
                } else if (mode == 1) {
                    float2 r2 = *reinterpret_cast<const float2*>(R + (size_t)m * Nn + ncol);
                    float2 o = make_float2(fmaxf(th * d0 + oth * r2.x, 0.f),
                                           fmaxf(th * d1 + oth * r2.y, 0.f));
                    *reinterpret_cast<float2*>(C + (size_t)m * Nn + ncol) = o;
                } else {
                    if (ncol < Nn)     C[(size_t)m * Nn + ncol]     = d0 + bias[ncol];
                    if (ncol + 1 < Nn) C[(size_t)m * Nn + ncol + 1] = d1 + bias[ncol + 1];
                }
            }
        }
    }
}

// ---------------- launch ----------------
extern "C" void kernel_launch(void* const* d_in, const int* in_sizes, int n_in,
                              void* d_out, int out_size) {
    const float* features = (const float*)d_in[0];
    const int*   erows    = (const int*)  d_in[1];
    const int*   ecols    = (const int*)  d_in[2];
    const float* evals    = (const float*)d_in[3];
    const float* W_in     = (const float*)d_in[4];
    const float* b_in     = (const float*)d_in[5];
    const float* convW    = (const float*)d_in[6];
    const float* W_out    = (const float*)d_in[7];
    const float* b_out    = (const float*)d_in[8];
    float* out = (float*)d_out;

    const int E = in_sizes[1];
    const int Mn = NNODES;

    float* d_h;   cudaGetSymbolAddress((void**)&d_h,   g_h);
    float* d_h0;  cudaGetSymbolAddress((void**)&d_h0,  g_h0);
    float* d_tmp; cudaGetSymbolAddress((void**)&d_tmp, g_tmp);

    cudaFuncSetAttribute(k_tgemm, cudaFuncAttributeMaxDynamicSharedMemorySize, SMEM_BYTES);

    // ---- build CSR ----
    int np1 = Mn + 1;
    k_zero_counts<<<(np1 + 255) / 256, 256>>>(np1);
    k_hist<<<(E + 255) / 256, 256>>>(erows, E);
    int nscan_blocks = (np1 + 1023) / 1024;
    k_scan_block<<<nscan_blocks, 1024>>>(np1);
    k_scan_partials<<<1, 1024>>>(nscan_blocks);
    k_scan_add<<<nscan_blocks, 1024>>>(np1);
    k_cursor<<<(Mn + 255) / 256, 256>>>(Mn);
    k_scatter<<<(E + 255) / 256, 256>>>(erows, ecols, evals, E);

    int mg = (Mn + BM - 1) / BM;

    // ---- input layer: h = relu(F @ W_in + b_in); h0 = h ----
    k_tgemm<<<dim3(mg, (NH + BN - 1) / BN), 256, SMEM_BYTES>>>(
        features, W_in, b_in, nullptr, 0.f, d_h, d_h0, Mn, NFEAT, NH, 0);

    // ---- GCNII layers ----
    for (int l = 0; l < NL; ++l) {
        float theta = logf(0.5f / (float)(l + 1) + 1.0f);
        k_spmm_combine<<<Mn / 2, 128>>>(d_h, d_h0, d_tmp);
        k_tgemm<<<dim3(mg, (NH + BN - 1) / BN), 256, SMEM_BYTES>>>(
            d_tmp, convW + (size_t)l * NH * NH, nullptr, d_tmp, theta,
            d_h, nullptr, Mn, NH, NH, 1);
    }

    // ---- output layer: out = h @ W_out + b_out ----
    k_tgemm<<<dim3(mg, (NC + BN - 1) / BN), 256, SMEM_BYTES>>>(
        d_h, W_out, b_out, nullptr, 0.f, out, nullptr, Mn, NH, NC, 2);
}

// round 4
// speedup vs baseline: 2.4255x; 1.1649x over previous
#include <cuda_runtime.h>
#include <cuda_bf16.h>
#include <math.h>
#include <stdint.h>

#define NNODES 100000
#define NEDGES 3200000
#define NFEAT  512
#define NH     256
#define NC     40
#define NL     8
#define ALPHA  0.1f

// ---------------- scratch (device globals; no allocation allowed) ----------------
__device__ __align__(16) float g_h  [(size_t)NNODES * NH];
__device__ __align__(16) float g_h0 [(size_t)NNODES * NH];
__device__ __align__(16) float g_tmp[(size_t)NNODES * NH];
__device__ __align__(16) __nv_bfloat16 g_hb[(size_t)NNODES * NH];
__device__ int   g_rowptr[NNODES + 1];
__device__ int   g_cursor[NNODES];
__device__ int   g_colidx[NEDGES];
__device__ float g_evals [NEDGES];
__device__ int   g_partial[1024];

__device__ __forceinline__ float tf32_rna(float x) {
    uint32_t u;
    asm("cvt.rna.tf32.f32 %0, %1;" : "=r"(u) : "f"(x));
    return __uint_as_float(u);
}

// ---------------- CSR construction ----------------
__global__ void k_zero_counts(int n) {
    for (int i = blockIdx.x * blockDim.x + threadIdx.x; i < n; i += gridDim.x * blockDim.x)
        g_rowptr[i] = 0;
}
__global__ void k_hist(const int* __restrict__ rows, int e) {
    for (int i = blockIdx.x * blockDim.x + threadIdx.x; i < e; i += gridDim.x * blockDim.x)
        atomicAdd(&g_rowptr[rows[i] + 1], 1);
}
__global__ void k_scan_block(int n) {
    __shared__ int s[1024];
    int i = blockIdx.x * 1024 + threadIdx.x;
    int v = (i < n) ? g_rowptr[i] : 0;
    s[threadIdx.x] = v;
    __syncthreads();
    #pragma unroll
    for (int off = 1; off < 1024; off <<= 1) {
        int t = (threadIdx.x >= off) ? s[threadIdx.x - off] : 0;
        __syncthreads();
        s[threadIdx.x] += t;
        __syncthreads();
    }
    if (i < n) g_rowptr[i] = s[threadIdx.x];
    if (threadIdx.x == 1023) g_partial[blockIdx.x] = s[1023];
}
__global__ void k_scan_partials(int nb) {
    __shared__ int s[1024];
    int v = (threadIdx.x < nb) ? g_partial[threadIdx.x] : 0;
    s[threadIdx.x] = v;
    __syncthreads();
    #pragma unroll
    for (int off = 1; off < 1024; off <<= 1) {
        int t = (threadIdx.x >= off) ? s[threadIdx.x - off] : 0;
        __syncthreads();
        s[threadIdx.x] += t;
        __syncthreads();
    }
    if (threadIdx.x < nb) g_partial[threadIdx.x] = s[threadIdx.x];
}
__global__ void k_scan_add(int n) {
    int i = blockIdx.x * 1024 + threadIdx.x;
    if (i < n && blockIdx.x > 0) g_rowptr[i] += g_partial[blockIdx.x - 1];
}
__global__ void k_cursor(int n) {
    for (int i = blockIdx.x * blockDim.x + threadIdx.x; i < n; i += gridDim.x * blockDim.x)
        g_cursor[i] = g_rowptr[i];
}
__global__ void k_scatter(const int* __restrict__ rows, const int* __restrict__ cols,
                          const float* __restrict__ vals, int e) {
    for (int i = blockIdx.x * blockDim.x + threadIdx.x; i < e; i += gridDim.x * blockDim.x) {
        int r = rows[i];
        int p = atomicAdd(&g_cursor[r], 1);
        g_colidx[p] = cols[i];
        g_evals[p]  = vals[i];
    }
}

// ---------------- SpMM (bf16 gather) + residual: out = 0.9*(G@hb) + 0.1*h0 ----------------
// 128 threads/block, 4 rows/block, 32 lanes per row; each lane owns 8 features (one uint4).
__device__ __forceinline__ void bf2_fma(uint32_t w, float v, float& a0, float& a1) {
    a0 += v * __uint_as_float(w << 16);            // low bf16 -> even feature
    a1 += v * __uint_as_float(w & 0xFFFF0000u);    // high bf16 -> odd feature
}

__global__ void __launch_bounds__(128)
k_spmm_combine(const __nv_bfloat16* __restrict__ hb, const float* __restrict__ h0,
               float* __restrict__ out) {
    int row  = blockIdx.x * 4 + (threadIdx.x >> 5);
    int lane = threadIdx.x & 31;
    const uint4* __restrict__ hb4 = (const uint4*)hb;    // row stride = 32 uint4

    int beg = g_rowptr[row], end = g_rowptr[row + 1];
    float acc[8] = {0.f, 0.f, 0.f, 0.f, 0.f, 0.f, 0.f, 0.f};

    int e = beg;
    for (; e + 4 <= end; e += 4) {
        int   c0 = g_colidx[e],     c1 = g_colidx[e + 1];
        int   c2 = g_colidx[e + 2], c3 = g_colidx[e + 3];
        float v0 = g_evals[e],      v1 = g_evals[e + 1];
        float v2 = g_evals[e + 2],  v3 = g_evals[e + 3];
        uint4 x0 = hb4[c0 * 32 + lane];
        uint4 x1 = hb4[c1 * 32 + lane];
        uint4 x2 = hb4[c2 * 32 + lane];
        uint4 x3 = hb4[c3 * 32 + lane];
        bf2_fma(x0.x, v0, acc[0], acc[1]); bf2_fma(x0.y, v0, acc[2], acc[3]);
        bf2_fma(x0.z, v0, acc[4], acc[5]); bf2_fma(x0.w, v0, acc[6], acc[7]);
        bf2_fma(x1.x, v1, acc[0], acc[1]); bf2_fma(x1.y, v1, acc[2], acc[3]);
        bf2_fma(x1.z, v1, acc[4], acc[5]); bf2_fma(x1.w, v1, acc[6], acc[7]);
        bf2_fma(x2.x, v2, acc[0], acc[1]); bf2_fma(x2.y, v2, acc[2], acc[3]);
        bf2_fma(x2.z, v2, acc[4], acc[5]); bf2_fma(x2.w, v2, acc[6], acc[7]);
        bf2_fma(x3.x, v3, acc[0], acc[1]); bf2_fma(x3.y, v3, acc[2], acc[3]);
        bf2_fma(x3.z, v3, acc[4], acc[5]); bf2_fma(x3.w, v3, acc[6], acc[7]);
    }
    for (; e < end; ++e) {
        int c = g_colidx[e];
        float v = g_evals[e];
        uint4 x = hb4[c * 32 + lane];
        bf2_fma(x.x, v, acc[0], acc[1]); bf2_fma(x.y, v, acc[2], acc[3]);
        bf2_fma(x.z, v, acc[4], acc[5]); bf2_fma(x.w, v, acc[6], acc[7]);
    }

    const float4* __restrict__ h04 = (const float4*)h0;  // row stride = 64 float4
    float4* __restrict__ o4 = (float4*)out;
    float4 z0 = h04[(size_t)row * 64 + lane * 2];
    float4 z1 = h04[(size_t)row * 64 + lane * 2 + 1];
    float4 oA, oB;
    oA.x = (1.f - ALPHA) * acc[0] + ALPHA * z0.x;
    oA.y = (1.f - ALPHA) * acc[1] + ALPHA * z0.y;
    oA.z = (1.f - ALPHA) * acc[2] + ALPHA * z0.z;
    oA.w = (1.f - ALPHA) * acc[3] + ALPHA * z0.w;
    oB.x = (1.f - ALPHA) * acc[4] + ALPHA * z1.x;
    oB.y = (1.f - ALPHA) * acc[5] + ALPHA * z1.y;
    oB.z = (1.f - ALPHA) * acc[6] + ALPHA * z1.z;
    oB.w = (1.f - ALPHA) * acc[7] + ALPHA * z1.w;
    o4[(size_t)row * 64 + lane * 2]     = oA;
    o4[(size_t)row * 64 + lane * 2 + 1] = oB;
}

// ---------------- tf32 mma.sync GEMM ----------------
// C[M,Nn] = A[M,K] @ B[K,Nn]  (both row-major; B fed as mma's col-major operand)
// mode 0: C = relu(D + bias), C2 = C, Cb = bf16(C)
// mode 1: C = relu(th*D + (1-th)*R), Cb = bf16(C) if non-null
// mode 2: C = D + bias
#define BM 128
#define BN 128
#define KC 32
#define ASTRIDE 36
#define BSTRIDE 136
#define A_ELEMS (BM * ASTRIDE)
#define B_ELEMS (KC * BSTRIDE)
#define SMEM_BYTES ((2 * A_ELEMS + 2 * B_ELEMS) * 4)

__device__ __forceinline__ void mma_tf32(float& c0, float& c1, float& c2, float& c3,
                                         uint32_t a0, uint32_t a1, uint32_t a2, uint32_t a3,
                                         uint32_t b0, uint32_t b1) {
    asm volatile(
        "mma.sync.aligned.m16n8k8.row.col.f32.tf32.tf32.f32 "
        "{%0,%1,%2,%3}, {%4,%5,%6,%7}, {%8,%9}, {%0,%1,%2,%3};"
        : "+f"(c0), "+f"(c1), "+f"(c2), "+f"(c3)
        : "r"(a0), "r"(a1), "r"(a2), "r"(a3), "r"(b0), "r"(b1));
}

__device__ __forceinline__ float4 cvt4(float4 v) {
    v.x = tf32_rna(v.x); v.y = tf32_rna(v.y);
    v.z = tf32_rna(v.z); v.w = tf32_rna(v.w);
    return v;
}

__global__ void __launch_bounds__(256, 1)
k_tgemm(const float* __restrict__ A, const float* __restrict__ B,
        const float* __restrict__ bias, const float* __restrict__ R,
        float th, float* __restrict__ C, float* __restrict__ C2,
        __nv_bfloat16* __restrict__ Cb,
        int M, int K, int Nn, int mode) {
    extern __shared__ float sm[];
    float* smA = sm;                       // [2][BM][ASTRIDE]
    float* smB = sm + 2 * A_ELEMS;         // [2][KC][BSTRIDE]

    int tid  = threadIdx.x;
    int wid  = tid >> 5, lane = tid & 31;
    int g    = lane >> 2, t = lane & 3;
    int wm   = wid & 1;
    int wn   = wid >> 1;
    int m0   = blockIdx.x * BM;
    int n0   = blockIdx.y * BN;
    int nc   = K / KC;

    float c[4][4][4];
    #pragma unroll
    for (int i = 0; i < 4; ++i)
        #pragma unroll
        for (int j = 0; j < 4; ++j)
            #pragma unroll
            for (int q = 0; q < 4; ++q) c[i][j][q] = 0.f;

    // ---- stage chunk 0 ----
    {
        #pragma unroll
        for (int p = 0; p < 4; ++p) {
            int idx = tid + p * 256;
            int r = idx >> 3, c4 = (idx & 7) << 2;
            float4 v = make_float4(0.f, 0.f, 0.f, 0.f);
            int gm = m0 + r;
            if (gm < M) v = *reinterpret_cast<const float4*>(A + (size_t)gm * K + c4);
            *reinterpret_cast<float4*>(&smA[r * ASTRIDE + c4]) = cvt4(v);
        }
        #pragma unroll
        for (int p = 0; p < 4; ++p) {
            int idx = tid + p * 256;
            int r = idx >> 5, c4 = (idx & 31) << 2;
            int gn = n0 + c4;
            float4 v = make_float4(0.f, 0.f, 0.f, 0.f);
            if (gn + 3 < Nn) {
                v = *reinterpret_cast<const float4*>(B + (size_t)r * Nn + gn);
            } else if (gn < Nn) {
                float tmp[4] = {0.f, 0.f, 0.f, 0.f};
                for (int q = 0; q < 4; ++q)
                    if (gn + q < Nn) tmp[q] = B[(size_t)r * Nn + gn + q];
                v = make_float4(tmp[0], tmp[1], tmp[2], tmp[3]);
            }
            *reinterpret_cast<float4*>(&smB[r * BSTRIDE + c4]) = cvt4(v);
        }
    }
    __syncthreads();

    for (int ch = 0; ch < nc; ++ch) {
        int buf = ch & 1;
        const float* As = smA + buf * A_ELEMS;
        const float* Bs = smB + buf * B_ELEMS;

        float4 pa[4], pb[4];
        bool more = (ch + 1 < nc);
        if (more) {
            int k0 = (ch + 1) * KC;
            #pragma unroll
            for (int p = 0; p < 4; ++p) {
                int idx = tid + p * 256;
                int r = idx >> 3, c4 = (idx & 7) << 2;
                pa[p] = make_float4(0.f, 0.f, 0.f, 0.f);
                int gm = m0 + r;
                if (gm < M)
                    pa[p] = *reinterpret_cast<const float4*>(A + (size_t)gm * K + k0 + c4);
            }
            #pragma unroll
            for (int p = 0; p < 4; ++p) {
                int idx = tid + p * 256;
                int r = idx >> 5, c4 = (idx & 31) << 2;
                int gn = n0 + c4;
                pb[p] = make_float4(0.f, 0.f, 0.f, 0.f);
                if (gn + 3 < Nn) {
                    pb[p] = *reinterpret_cast<const float4*>(B + (size_t)(k0 + r) * Nn + gn);
                } else if (gn < Nn) {
                    float tmp[4] = {0.f, 0.f, 0.f, 0.f};
                    for (int q = 0; q < 4; ++q)
                        if (gn + q < Nn) tmp[q] = B[(size_t)(k0 + r) * Nn + gn + q];
                    pb[p] = make_float4(tmp[0], tmp[1], tmp[2], tmp[3]);
                }
            }
        }

        #pragma unroll
        for (int ks = 0; ks < 4; ++ks) {
            int kk = ks * 8;
            uint32_t af[4][4];
            #pragma unroll
            for (int mf = 0; mf < 4; ++mf) {
                int r = wm * 64 + mf * 16 + g;
                af[mf][0] = __float_as_uint(As[(r    ) * ASTRIDE + kk + t    ]);
                af[mf][1] = __float_as_uint(As[(r + 8) * ASTRIDE + kk + t    ]);
                af[mf][2] = __float_as_uint(As[(r    ) * ASTRIDE + kk + t + 4]);
                af[mf][3] = __float_as_uint(As[(r + 8) * ASTRIDE + kk + t + 4]);
            }
            uint32_t bf[4][2];
            #pragma unroll
            for (int nf = 0; nf < 4; ++nf) {
                int ncol = wn * 32 + nf * 8 + g;
                bf[nf][0] = __float_as_uint(Bs[(kk + t    ) * BSTRIDE + ncol]);
                bf[nf][1] = __float_as_uint(Bs[(kk + t + 4) * BSTRIDE + ncol]);
            }
            #pragma unroll
            for (int mf = 0; mf < 4; ++mf)
                #pragma unroll
                for (int nf = 0; nf < 4; ++nf)
                    mma_tf32(c[mf][nf][0], c[mf][nf][1], c[mf][nf][2], c[mf][nf][3],
                             af[mf][0], af[mf][1], af[mf][2], af[mf][3],
                             bf[nf][0], bf[nf][1]);
        }

        if (more) {
            float* Ad = smA + (buf ^ 1) * A_ELEMS;
            float* Bd = smB + (buf ^ 1) * B_ELEMS;
            #pragma unroll
            for (int p = 0; p < 4; ++p) {
                int idx = tid + p * 256;
                int r = idx >> 3, c4 = (idx & 7) << 2;
                *reinterpret_cast<float4*>(&Ad[r * ASTRIDE + c4]) = cvt4(pa[p]);
            }
            #pragma unroll
            for (int p = 0; p < 4; ++p) {
                int idx = tid + p * 256;
                int r = idx >> 5, c4 = (idx & 31) << 2;
                *reinterpret_cast<float4*>(&Bd[r * BSTRIDE + c4]) = cvt4(pb[p]);
            }
        }
        __syncthreads();
    }

    // ---- epilogue ----
    float oth = 1.f - th;
    #pragma unroll
    for (int mf = 0; mf < 4; ++mf) {
        int r0 = m0 + wm * 64 + mf * 16 + g;
        #pragma unroll
        for (int nf = 0; nf < 4; ++nf) {
            int ncol = n0 + wn * 32 + nf * 8 + 2 * t;
            #pragma unroll
            for (int half = 0; half < 2; ++half) {
                int m = r0 + half * 8;
                if (m >= M) continue;
                float d0 = c[mf][nf][half * 2 + 0];
                float d1 = c[mf][nf][half * 2 + 1];
                if (mode == 0) {
                    float o0 = fmaxf(d0 + bias[ncol], 0.f);
                    float o1 = fmaxf(d1 + bias[ncol + 1], 0.f);
                    float2 o = make_float2(o0, o1);
                    *reinterpret_cast<float2*>(C  + (size_t)m * Nn + ncol) = o;
                    *reinterpret_cast<float2*>(C2 + (size_t)m * Nn + ncol) = o;
                    *reinterpret_cast<__nv_bfloat162*>(Cb + (size_t)m * Nn + ncol) =
                        __float22bfloat162_rn(o);
                } else if (mode == 1) {
                    float2 r2 = *reinterpret_cast<const float2*>(R + (size_t)m * Nn + ncol);
                    float2 o = make_float2(fmaxf(th * d0 + oth * r2.x, 0.f),
                                           fmaxf(th * d1 + oth * r2.y, 0.f));
                    *reinterpret_cast<float2*>(C + (size_t)m * Nn + ncol) = o;
                    if (Cb)
                        *reinterpret_cast<__nv_bfloat162*>(Cb + (size_t)m * Nn + ncol) =
                            __float22bfloat162_rn(o);
                } else {
                    if (ncol < Nn)     C[(size_t)m * Nn + ncol]     = d0 + bias[ncol];
                    if (ncol + 1 < Nn) C[(size_t)m * Nn + ncol + 1] = d1 + bias[ncol + 1];
                }
            }
        }
    }
}

// ---------------- launch ----------------
extern "C" void kernel_launch(void* const* d_in, const int* in_sizes, int n_in,
                              void* d_out, int out_size) {
    const float* features = (const float*)d_in[0];
    const int*   erows    = (const int*)  d_in[1];
    const int*   ecols    = (const int*)  d_in[2];
    const float* evals    = (const float*)d_in[3];
    const float* W_in     = (const float*)d_in[4];
    const float* b_in     = (const float*)d_in[5];
    const float* convW    = (const float*)d_in[6];
    const float* W_out    = (const float*)d_in[7];
    const float* b_out    = (const float*)d_in[8];
    float* out = (float*)d_out;

    const int E = in_sizes[1];
    const int Mn = NNODES;

    float* d_h;   cudaGetSymbolAddress((void**)&d_h,   g_h);
    float* d_h0;  cudaGetSymbolAddress((void**)&d_h0,  g_h0);
    float* d_tmp; cudaGetSymbolAddress((void**)&d_tmp, g_tmp);
    __nv_bfloat16* d_hb; cudaGetSymbolAddress((void**)&d_hb, g_hb);

    cudaFuncSetAttribute(k_tgemm, cudaFuncAttributeMaxDynamicSharedMemorySize, SMEM_BYTES);

    // ---- build CSR ----
    int np1 = Mn + 1;
    k_zero_counts<<<(np1 + 255) / 256, 256>>>(np1);
    k_hist<<<(E + 255) / 256, 256>>>(erows, E);
    int nscan_blocks = (np1 + 1023) / 1024;
    k_scan_block<<<nscan_blocks, 1024>>>(np1);
    k_scan_partials<<<1, 1024>>>(nscan_blocks);
    k_scan_add<<<nscan_blocks, 1024>>>(np1);
    k_cursor<<<(Mn + 255) / 256, 256>>>(Mn);
    k_scatter<<<(E + 255) / 256, 256>>>(erows, ecols, evals, E);

    int mg = (Mn + BM - 1) / BM;

    // ---- input layer: h = relu(F @ W_in + b_in); h0 = h; hb = bf16(h) ----
    k_tgemm<<<dim3(mg, (NH + BN - 1) / BN), 256, SMEM_BYTES>>>(
        features, W_in, b_in, nullptr, 0.f, d_h, d_h0, d_hb, Mn, NFEAT, NH, 0);

    // ---- GCNII layers ----
    for (int l = 0; l < NL; ++l) {
        float theta = logf(0.5f / (float)(l + 1) + 1.0f);
        k_spmm_combine<<<Mn / 4, 128>>>(d_hb, d_h0, d_tmp);
        k_tgemm<<<dim3(mg, (NH + BN - 1) / BN), 256, SMEM_BYTES>>>(
            d_tmp, convW + (size_t)l * NH * NH, nullptr, d_tmp, theta,
            d_h, nullptr, (l + 1 < NL) ? d_hb : nullptr, Mn, NH, NH, 1);
    }

    // ---- output layer: out = h @ W_out + b_out ----
    k_tgemm<<<dim3(mg, (NC + BN - 1) / BN), 256, SMEM_BYTES>>>(
        d_h, W_out, b_out, nullptr, 0.f, out, nullptr, nullptr, Mn, NH, NC, 2);
}

// round 5
// speedup vs baseline: 2.6396x; 1.0883x over previous
#include <cuda_runtime.h>
#include <cuda_bf16.h>
#include <math.h>
#include <stdint.h>

#define NNODES 100000
#define NEDGES 3200000
#define NFEAT  512
#define NH     256
#define NC     40
#define NL     8
#define ALPHA  0.1f

// ---------------- scratch (device globals; no allocation allowed) ----------------
__device__ __align__(16) float g_h  [(size_t)NNODES * NH];
__device__ __align__(16) float g_h0 [(size_t)NNODES * NH];
__device__ __align__(16) float g_tmp[(size_t)NNODES * NH];
__device__ __align__(16) __nv_bfloat16 g_hb[(size_t)NNODES * NH];
__device__ __align__(16) int2 g_edge[NEDGES];      // packed (col, val bits)
__device__ int   g_rowptr[NNODES + 1];
__device__ int   g_cursor[NNODES];
__device__ int   g_partial[1024];

__device__ __forceinline__ uint32_t smem_u32(const void* p) {
    uint32_t a;
    asm("{ .reg .u64 t; cvta.to.shared.u64 t, %1; cvt.u32.u64 %0, t; }" : "=r"(a) : "l"(p));
    return a;
}
__device__ __forceinline__ uint32_t tf32_u(float x) {
    uint32_t u;
    asm("cvt.rna.tf32.f32 %0, %1;" : "=r"(u) : "f"(x));
    return u;
}
__device__ __forceinline__ void cp16(uint32_t dst, const void* src, int bytes) {
    asm volatile("cp.async.ca.shared.global [%0], [%1], 16, %2;"
                 :: "r"(dst), "l"(src), "r"(bytes) : "memory");
}
#define CP_COMMIT() asm volatile("cp.async.commit_group;" ::: "memory")
#define CP_WAIT1()  asm volatile("cp.async.wait_group 1;" ::: "memory")
#define CP_WAIT0()  asm volatile("cp.async.wait_group 0;" ::: "memory")

// ---------------- CSR construction ----------------
__global__ void k_zero_counts(int n) {
    for (int i = blockIdx.x * blockDim.x + threadIdx.x; i < n; i += gridDim.x * blockDim.x)
        g_rowptr[i] = 0;
}
__global__ void k_hist(const int* __restrict__ rows, int e) {
    for (int i = blockIdx.x * blockDim.x + threadIdx.x; i < e; i += gridDim.x * blockDim.x)
        atomicAdd(&g_rowptr[rows[i] + 1], 1);
}
__global__ void k_scan_block(int n) {
    __shared__ int s[1024];
    int i = blockIdx.x * 1024 + threadIdx.x;
    int v = (i < n) ? g_rowptr[i] : 0;
    s[threadIdx.x] = v;
    __syncthreads();
    #pragma unroll
    for (int off = 1; off < 1024; off <<= 1) {
        int t = (threadIdx.x >= off) ? s[threadIdx.x - off] : 0;
        __syncthreads();
        s[threadIdx.x] += t;
        __syncthreads();
    }
    if (i < n) g_rowptr[i] = s[threadIdx.x];
    if (threadIdx.x == 1023) g_partial[blockIdx.x] = s[1023];
}
__global__ void k_scan_partials(int nb) {
    __shared__ int s[1024];
    int v = (threadIdx.x < nb) ? g_partial[threadIdx.x] : 0;
    s[threadIdx.x] = v;
    __syncthreads();
    #pragma unroll
    for (int off = 1; off < 1024; off <<= 1) {
        int t = (threadIdx.x >= off) ? s[threadIdx.x - off] : 0;
        __syncthreads();
        s[threadIdx.x] += t;
        __syncthreads();
    }
    if (threadIdx.x < nb) g_partial[threadIdx.x] = s[threadIdx.x];
}
__global__ void k_scan_add(int n) {
    int i = blockIdx.x * 1024 + threadIdx.x;
    if (i < n && blockIdx.x > 0) g_rowptr[i] += g_partial[blockIdx.x - 1];
}
__global__ void k_cursor(int n) {
    for (int i = blockIdx.x * blockDim.x + threadIdx.x; i < n; i += gridDim.x * blockDim.x)
        g_cursor[i] = g_rowptr[i];
}
__global__ void k_scatter(const int* __restrict__ rows, const int* __restrict__ cols,
                          const float* __restrict__ vals, int e) {
    for (int i = blockIdx.x * blockDim.x + threadIdx.x; i < e; i += gridDim.x * blockDim.x) {
        int r = rows[i];
        int p = atomicAdd(&g_cursor[r], 1);
        g_edge[p] = make_int2(cols[i], __float_as_int(vals[i]));
    }
}

// ---------------- SpMM (bf16 gather) + residual: out = 0.9*(G@hb) + 0.1*h0 ----------------
// 128 threads/block, 4 rows/block, 32 lanes per row; each lane owns 8 features (one uint4).
__device__ __forceinline__ void bf2_fma(uint32_t w, float v, float& a0, float& a1) {
    a0 += v * __uint_as_float(w << 16);
    a1 += v * __uint_as_float(w & 0xFFFF0000u);
}
__device__ __forceinline__ void acc_edge(uint4 x, float v, float* acc) {
    bf2_fma(x.x, v, acc[0], acc[1]); bf2_fma(x.y, v, acc[2], acc[3]);
    bf2_fma(x.z, v, acc[4], acc[5]); bf2_fma(x.w, v, acc[6], acc[7]);
}

__global__ void __launch_bounds__(128)
k_spmm_combine(const __nv_bfloat16* __restrict__ hb, const float* __restrict__ h0,
               float* __restrict__ out) {
    int row  = blockIdx.x * 4 + (threadIdx.x >> 5);
    int lane = threadIdx.x & 31;
    const uint4* __restrict__ hb4 = (const uint4*)hb;    // row stride = 32 uint4

    int beg = g_rowptr[row], end = g_rowptr[row + 1];
    float acc[8] = {0.f, 0.f, 0.f, 0.f, 0.f, 0.f, 0.f, 0.f};

    int e = beg;
    for (; e + 8 <= end; e += 8) {
        int2 E0 = g_edge[e],     E1 = g_edge[e + 1];
        int2 E2 = g_edge[e + 2], E3 = g_edge[e + 3];
        int2 E4 = g_edge[e + 4], E5 = g_edge[e + 5];
        int2 E6 = g_edge[e + 6], E7 = g_edge[e + 7];
        uint4 x0 = hb4[E0.x * 32 + lane];
        uint4 x1 = hb4[E1.x * 32 + lane];
        uint4 x2 = hb4[E2.x * 32 + lane];
        uint4 x3 = hb4[E3.x * 32 + lane];
        uint4 x4 = hb4[E4.x * 32 + lane];
        uint4 x5 = hb4[E5.x * 32 + lane];
        uint4 x6 = hb4[E6.x * 32 + lane];
        uint4 x7 = hb4[E7.x * 32 + lane];
        acc_edge(x0, __int_as_float(E0.y), acc);
        acc_edge(x1, __int_as_float(E1.y), acc);
        acc_edge(x2, __int_as_float(E2.y), acc);
        acc_edge(x3, __int_as_float(E3.y), acc);
        acc_edge(x4, __int_as_float(E4.y), acc);
        acc_edge(x5, __int_as_float(E5.y), acc);
        acc_edge(x6, __int_as_float(E6.y), acc);
        acc_edge(x7, __int_as_float(E7.y), acc);
    }
    for (; e < end; ++e) {
        int2 E = g_edge[e];
        uint4 x = hb4[E.x * 32 + lane];
        acc_edge(x, __int_as_float(E.y), acc);
    }

    const float4* __restrict__ h04 = (const float4*)h0;  // row stride = 64 float4
    float4* __restrict__ o4 = (float4*)out;
    float4 z0 = h04[(size_t)row * 64 + lane * 2];
    float4 z1 = h04[(size_t)row * 64 + lane * 2 + 1];
    float4 oA, oB;
    oA.x = (1.f - ALPHA) * acc[0] + ALPHA * z0.x;
    oA.y = (1.f - ALPHA) * acc[1] + ALPHA * z0.y;
    oA.z = (1.f - ALPHA) * acc[2] + ALPHA * z0.z;
    oA.w = (1.f - ALPHA) * acc[3] + ALPHA * z0.w;
    oB.x = (1.f - ALPHA) * acc[4] + ALPHA * z1.x;
    oB.y = (1.f - ALPHA) * acc[5] + ALPHA * z1.y;
    oB.z = (1.f - ALPHA) * acc[6] + ALPHA * z1.z;
    oB.w = (1.f - ALPHA) * acc[7] + ALPHA * z1.w;
    o4[(size_t)row * 64 + lane * 2]     = oA;
    o4[(size_t)row * 64 + lane * 2 + 1] = oB;
}

// ---------------- tf32 mma.sync GEMM with cp.async double-buffer ----------------
// C[M,Nn] = A[M,K] @ B[K,Nn]  (both row-major; B fed as mma's col-major operand)
// mode 0: C = relu(D + bias), C2 = C, Cb = bf16(C)
// mode 1: C = relu(th*D + (1-th)*R), Cb = bf16(C) if non-null
// mode 2: C = D + bias
#define BM 128
#define BN 128
#define KC 32
#define ASTRIDE 36
#define BSTRIDE 136
#define A_ELEMS (BM * ASTRIDE)
#define B_ELEMS (KC * BSTRIDE)
#define SMEM_BYTES ((2 * A_ELEMS + 2 * B_ELEMS) * 4)

__device__ __forceinline__ void mma_tf32(float& c0, float& c1, float& c2, float& c3,
                                         uint32_t a0, uint32_t a1, uint32_t a2, uint32_t a3,
                                         uint32_t b0, uint32_t b1) {
    asm volatile(
        "mma.sync.aligned.m16n8k8.row.col.f32.tf32.tf32.f32 "
        "{%0,%1,%2,%3}, {%4,%5,%6,%7}, {%8,%9}, {%0,%1,%2,%3};"
        : "+f"(c0), "+f"(c1), "+f"(c2), "+f"(c3)
        : "r"(a0), "r"(a1), "r"(a2), "r"(a3), "r"(b0), "r"(b1));
}

__global__ void __launch_bounds__(256, 2)
k_tgemm(const float* __restrict__ A, const float* __restrict__ B,
        const float* __restrict__ bias, const float* __restrict__ R,
        float th, float* __restrict__ C, float* __restrict__ C2,
        __nv_bfloat16* __restrict__ Cb,
        int M, int K, int Nn, int mode) {
    extern __shared__ float sm[];
    float* smA = sm;                       // [2][BM][ASTRIDE]
    float* smB = sm + 2 * A_ELEMS;         // [2][KC][BSTRIDE]
    uint32_t sA = smem_u32(smA);
    uint32_t sB = smem_u32(smB);

    int tid  = threadIdx.x;
    int wid  = tid >> 5, lane = tid & 31;
    int g    = lane >> 2, t = lane & 3;
    int wm   = wid & 1;
    int wn   = wid >> 1;
    int m0   = blockIdx.x * BM;
    int n0   = blockIdx.y * BN;
    int nc   = K / KC;

    // per-thread staging coordinates
    int ar  = tid >> 1;                    // A row 0..127
    int ac  = (tid & 1) << 4;              // A col-chunk {0,16}: 2 cp16 each
    int br  = tid >> 3;                    // B row 0..31
    int bc  = (tid & 7) << 4;              // B col {0,16,...,112}: 1 cp16

    const float* Asrc = A + (size_t)(m0 + ar) * K + ac;
    int abytes = (m0 + ar < M) ? 16 : 0;
    int gnb = n0 + bc;

    // stage chunk 0
    {
        cp16(sA + (ar * ASTRIDE + ac) * 4, Asrc, abytes);
        cp16(sA + (ar * ASTRIDE + ac + 4) * 4, Asrc + 4, abytes);
        cp16(sA + (ar * ASTRIDE + ac + 8) * 4, Asrc + 8, abytes);
        cp16(sA + (ar * ASTRIDE + ac + 12) * 4, Asrc + 12, abytes);
        #pragma unroll
        for (int q = 0; q < 4; ++q) {
            int gn = gnb + q * 4;
            int bbytes = (Nn - gn >= 4) ? 16 : ((Nn - gn > 0) ? (Nn - gn) * 4 : 0);
            cp16(sB + (br * BSTRIDE + bc + q * 4) * 4,
                 B + (size_t)br * Nn + ((bbytes > 0) ? gn : 0), bbytes);
        }
        CP_COMMIT();
    }

    float c[4][4][4];
    #pragma unroll
    for (int i = 0; i < 4; ++i)
        #pragma unroll
        for (int j = 0; j < 4; ++j)
            #pragma unroll
            for (int q = 0; q < 4; ++q) c[i][j][q] = 0.f;

    for (int ch = 0; ch < nc; ++ch) {
        int buf = ch & 1;
        bool more = (ch + 1 < nc);
        if (more) {
            int k0 = (ch + 1) * KC;
            int bo = (buf ^ 1);
            uint32_t dA = sA + (bo * A_ELEMS + ar * ASTRIDE + ac) * 4;
            const float* src = Asrc + k0;
            cp16(dA,      src,      abytes);
            cp16(dA + 16, src + 4,  abytes);
            cp16(dA + 32, src + 8,  abytes);
            cp16(dA + 48, src + 12, abytes);
            #pragma unroll
            for (int q = 0; q < 4; ++q) {
                int gn = gnb + q * 4;
                int bbytes = (Nn - gn >= 4) ? 16 : ((Nn - gn > 0) ? (Nn - gn) * 4 : 0);
                cp16(sB + (bo * B_ELEMS + br * BSTRIDE + bc + q * 4) * 4,
                     B + (size_t)(k0 + br) * Nn + ((bbytes > 0) ? gn : 0), bbytes);
            }
            CP_COMMIT();
            CP_WAIT1();
        } else {
            CP_WAIT0();
        }
        __syncthreads();

        const float* As = smA + buf * A_ELEMS;
        const float* Bs = smB + buf * B_ELEMS;
        #pragma unroll
        for (int ks = 0; ks < 4; ++ks) {
            int kk = ks * 8;
            uint32_t af[4][4];
            #pragma unroll
            for (int mf = 0; mf < 4; ++mf) {
                int r = wm * 64 + mf * 16 + g;
                af[mf][0] = tf32_u(As[(r    ) * ASTRIDE + kk + t    ]);
                af[mf][1] = tf32_u(As[(r + 8) * ASTRIDE + kk + t    ]);
                af[mf][2] = tf32_u(As[(r    ) * ASTRIDE + kk + t + 4]);
                af[mf][3] = tf32_u(As[(r + 8) * ASTRIDE + kk + t + 4]);
            }
            uint32_t bf[4][2];
            #pragma unroll
            for (int nf = 0; nf < 4; ++nf) {
                int ncol = wn * 32 + nf * 8 + g;
                bf[nf][0] = tf32_u(Bs[(kk + t    ) * BSTRIDE + ncol]);
                bf[nf][1] = tf32_u(Bs[(kk + t + 4) * BSTRIDE + ncol]);
            }
            #pragma unroll
            for (int mf = 0; mf < 4; ++mf)
                #pragma unroll
                for (int nf = 0; nf < 4; ++nf)
                    mma_tf32(c[mf][nf][0], c[mf][nf][1], c[mf][nf][2], c[mf][nf][3],
                             af[mf][0], af[mf][1], af[mf][2], af[mf][3],
                             bf[nf][0], bf[nf][1]);
        }
        __syncthreads();
    }

    // ---- epilogue ----
    float oth = 1.f - th;
    #pragma unroll
    for (int mf = 0; mf < 4; ++mf) {
        int r0 = m0 + wm * 64 + mf * 16 + g;
        #pragma unroll
        for (int nf = 0; nf < 4; ++nf) {
            int ncol = n0 + wn * 32 + nf * 8 + 2 * t;
            #pragma unroll
            for (int half = 0; half < 2; ++half) {
                int m = r0 + half * 8;
                if (m >= M) continue;
                float d0 = c[mf][nf][half * 2 + 0];
                float d1 = c[mf][nf][half * 2 + 1];
                if (mode == 0) {
                    float o0 = fmaxf(d0 + bias[ncol], 0.f);
                    float o1 = fmaxf(d1 + bias[ncol + 1], 0.f);
                    float2 o = make_float2(o0, o1);
                    *reinterpret_cast<float2*>(C  + (size_t)m * Nn + ncol) = o;
                    *reinterpret_cast<float2*>(C2 + (size_t)m * Nn + ncol) = o;
                    *reinterpret_cast<__nv_bfloat162*>(Cb + (size_t)m * Nn + ncol) =
                        __float22bfloat162_rn(o);
                } else if (mode == 1) {
                    float2 r2 = *reinterpret_cast<const float2*>(R + (size_t)m * Nn + ncol);
                    float2 o = make_float2(fmaxf(th * d0 + oth * r2.x, 0.f),
                                           fmaxf(th * d1 + oth * r2.y, 0.f));
                    *reinterpret_cast<float2*>(C + (size_t)m * Nn + ncol) = o;
                    if (Cb)
                        *reinterpret_cast<__nv_bfloat162*>(Cb + (size_t)m * Nn + ncol) =
                            __float22bfloat162_rn(o);
                } else {
                    if (ncol < Nn)     C[(size_t)m * Nn + ncol]     = d0 + bias[ncol];
                    if (ncol + 1 < Nn) C[(size_t)m * Nn + ncol + 1] = d1 + bias[ncol + 1];
                }
            }
        }
    }
}

// ---------------- launch ----------------
extern "C" void kernel_launch(void* const* d_in, const int* in_sizes, int n_in,
                              void* d_out, int out_size) {
    const float* features = (const float*)d_in[0];
    const int*   erows    = (const int*)  d_in[1];
    const int*   ecols    = (const int*)  d_in[2];
    const float* evals    = (const float*)d_in[3];
    const float* W_in     = (const float*)d_in[4];
    const float* b_in     = (const float*)d_in[5];
    const float* convW    = (const float*)d_in[6];
    const float* W_out    = (const float*)d_in[7];
    const float* b_out    = (const float*)d_in[8];
    float* out = (float*)d_out;

    const int E = in_sizes[1];
    const int Mn = NNODES;

    float* d_h;   cudaGetSymbolAddress((void**)&d_h,   g_h);
    float* d_h0;  cudaGetSymbolAddress((void**)&d_h0,  g_h0);
    float* d_tmp; cudaGetSymbolAddress((void**)&d_tmp, g_tmp);
    __nv_bfloat16* d_hb; cudaGetSymbolAddress((void**)&d_hb, g_hb);

    cudaFuncSetAttribute(k_tgemm, cudaFuncAttributeMaxDynamicSharedMemorySize, SMEM_BYTES);

    // ---- build CSR ----
    int np1 = Mn + 1;
    k_zero_counts<<<(np1 + 255) / 256, 256>>>(np1);
    k_hist<<<(E + 255) / 256, 256>>>(erows, E);
    int nscan_blocks = (np1 + 1023) / 1024;
    k_scan_block<<<nscan_blocks, 1024>>>(np1);
    k_scan_partials<<<1, 1024>>>(nscan_blocks);
    k_scan_add<<<nscan_blocks, 1024>>>(np1);
    k_cursor<<<(Mn + 255) / 256, 256>>>(Mn);
    k_scatter<<<(E + 255) / 256, 256>>>(erows, ecols, evals, E);

    int mg = (Mn + BM - 1) / BM;

    // ---- input layer: h = relu(F @ W_in + b_in); h0 = h; hb = bf16(h) ----
    k_tgemm<<<dim3(mg, (NH + BN - 1) / BN), 256, SMEM_BYTES>>>(
        features, W_in, b_in, nullptr, 0.f, d_h, d_h0, d_hb, Mn, NFEAT, NH, 0);

    // ---- GCNII layers ----
    for (int l = 0; l < NL; ++l) {
        float theta = logf(0.5f / (float)(l + 1) + 1.0f);
        k_spmm_combine<<<Mn / 4, 128>>>(d_hb, d_h0, d_tmp);
        k_tgemm<<<dim3(mg, (NH + BN - 1) / BN), 256, SMEM_BYTES>>>(
            d_tmp, convW + (size_t)l * NH * NH, nullptr, d_tmp, theta,
            d_h, nullptr, (l + 1 < NL) ? d_hb : nullptr, Mn, NH, NH, 1);
    }

    // ---- output layer: out = h @ W_out + b_out ----
    k_tgemm<<<dim3(mg, (NC + BN - 1) / BN), 256, SMEM_BYTES>>>(
        d_h, W_out, b_out, nullptr, 0.f, out, nullptr, nullptr, Mn, NH, NC, 2);
}